// round 9
// baseline (speedup 1.0000x reference)
#include <cuda_runtime.h>
#include <math.h>

// Problem constants
#define MROWS  16384   // B*T*S = 32*512
#define DMODEL 768
#define SEQ    512
#define NHEAD  12
#define HDIM   64
#define NBATCH 384     // (B*T)*H = 32*12

// ---------------- scratch (static device memory; no allocation) --------------
__device__ float g_Q  [(size_t)NBATCH * SEQ * HDIM];   // [b*h][s][d] (pre-scaled, tf32-rounded)
__device__ float g_Kt [(size_t)NBATCH * HDIM * SEQ];   // [b*h][d][s] (tf32-rounded)
__device__ float g_V  [(size_t)NBATCH * SEQ * HDIM];   // [b*h][s][d] (tf32-rounded)
__device__ float g_CTX[(size_t)MROWS * DMODEL];        // [row][h*64+d] (tf32-rounded)
__device__ float g_Xr [(size_t)MROWS * DMODEL];        // tf32-rounded x
__device__ float g_Wr [(size_t)4 * DMODEL * DMODEL];   // tf32-rounded Wq,Wk,Wv,Wo

// ---------------- helpers ----------------
__device__ __forceinline__ unsigned f2tf(float f) {
    unsigned u;
    asm("cvt.rna.tf32.f32 %0, %1;" : "=r"(u) : "f"(f));
    return u;
}
__device__ __forceinline__ float f2tff(float f) { return __uint_as_float(f2tf(f)); }

__device__ __forceinline__ void cp16(unsigned dst, const void* src) {
    asm volatile("cp.async.ca.shared.global [%0], [%1], 16;" :: "r"(dst), "l"(src));
}

#define MMA_TF32(d, a, b)                                                          \
    asm volatile(                                                                  \
        "mma.sync.aligned.m16n8k8.row.col.f32.tf32.tf32.f32 "                      \
        "{%0,%1,%2,%3}, {%4,%5,%6,%7}, {%8,%9}, {%0,%1,%2,%3};"                    \
        : "+f"((d)[0]), "+f"((d)[1]), "+f"((d)[2]), "+f"((d)[3])                   \
        : "r"((a)[0]), "r"((a)[1]), "r"((a)[2]), "r"((a)[3]),                      \
          "r"((b)[0]), "r"((b)[1]))

// =============================================================================
// prep: tf32-round x and the 4 weight matrices into scratch (float4 grid).
// =============================================================================
#define XQUADS ((MROWS * DMODEL) / 4)        // 3145728
#define WQUADS ((DMODEL * DMODEL) / 4)       // 147456
#define PREP_QUADS (XQUADS + 4 * WQUADS)

__global__ __launch_bounds__(256) void prep_round(
    const float* __restrict__ x,  const float* __restrict__ Wq,
    const float* __restrict__ Wk, const float* __restrict__ Wv,
    const float* __restrict__ Wo)
{
    int i = blockIdx.x * 256 + threadIdx.x;
    if (i >= PREP_QUADS) return;
    const float4* src;
    float4* dst;
    if (i < XQUADS) {
        src = (const float4*)x + i;
        dst = (float4*)g_Xr + i;
    } else {
        int j = i - XQUADS;
        int w = j / WQUADS, o = j - w * WQUADS;
        const float* ws = (w == 0) ? Wq : (w == 1) ? Wk : (w == 2) ? Wv : Wo;
        src = (const float4*)ws + o;
        dst = (float4*)(g_Wr + (size_t)w * DMODEL * DMODEL) + o;
    }
    float4 v = *src;
    v.x = f2tff(v.x); v.y = f2tff(v.y); v.z = f2tff(v.z); v.w = f2tff(v.w);
    *dst = v;
}

// scatter for projection GEMM epilogues (rounds for modes 0-2)
__device__ __forceinline__ void scatter(int mode, int m, int n, float v,
                                        float* __restrict__ out) {
    int bt = m >> 9, s = m & 511;
    int h = n >> 6, d = n & 63;
    if (mode == 0) {
        g_Q[((size_t)(bt * NHEAD + h) * SEQ + s) * HDIM + d] = f2tff(v * 0.125f);
    } else if (mode == 1) {
        g_Kt[((size_t)(bt * NHEAD + h) * HDIM + d) * SEQ + s] = f2tff(v);
    } else if (mode == 2) {
        g_V[((size_t)(bt * NHEAD + h) * SEQ + s) * HDIM + d] = f2tff(v);
    } else {
        out[(size_t)m * DMODEL + n] = v;
    }
}

// =============================================================================
// 128x128 tf32-MMA GEMM over K=768, cp.async double-buffered, 2 blocks/SM.
// Inputs pre-rounded -> zero CVT in the inner loop.
// =============================================================================
#define SA_STR 20
#define SB_STR 136
#define SA_SZ  (128 * SA_STR)
#define SB_SZ  (16 * SB_STR)

__global__ __launch_bounds__(256, 2) void gemm768(
    const float* __restrict__ bias, float* __restrict__ out, int mode)
{
    __shared__ float sA[2 * SA_SZ];
    __shared__ float sB[2 * SB_SZ];

    const float* __restrict__ A = (mode == 3) ? (const float*)g_CTX : (const float*)g_Xr;
    const float* __restrict__ W = g_Wr + (size_t)mode * DMODEL * DMODEL;

    const int tid  = threadIdx.x;
    const int lane = tid & 31, warp = tid >> 5;
    const int wm = warp & 1, wn = warp >> 1;
    const int grp = lane >> 2, tig = lane & 3;
    const int m0 = blockIdx.y * 128;
    const int n0 = blockIdx.x * 128;

    const unsigned sA_u32 = (unsigned)__cvta_generic_to_shared(sA);
    const unsigned sB_u32 = (unsigned)__cvta_generic_to_shared(sB);

    float acc[4][4][4];
#pragma unroll
    for (int i = 0; i < 4; i++)
#pragma unroll
        for (int j = 0; j < 4; j++)
#pragma unroll
            for (int e = 0; e < 4; e++) acc[i][j][e] = 0.0f;

#define G_LOAD_TILES(buf, k0)                                                     \
    {                                                                             \
        _Pragma("unroll")                                                         \
        for (int rep = 0; rep < 2; rep++) {                                       \
            int t = rep * 256 + tid;                                              \
            int r = t >> 2, c4 = (t & 3) * 4;                                     \
            cp16(sA_u32 + (unsigned)(((buf) * SA_SZ + r * SA_STR + c4) * 4),      \
                 A + (size_t)(m0 + r) * DMODEL + (k0) + c4);                      \
        }                                                                         \
        _Pragma("unroll")                                                         \
        for (int rep = 0; rep < 2; rep++) {                                       \
            int t = rep * 256 + tid;                                              \
            int r = t >> 5, c4 = (t & 31) * 4;                                    \
            cp16(sB_u32 + (unsigned)(((buf) * SB_SZ + r * SB_STR + c4) * 4),      \
                 W + (size_t)((k0) + r) * DMODEL + n0 + c4);                      \
        }                                                                         \
        asm volatile("cp.async.commit_group;" ::: "memory");                      \
    }

    G_LOAD_TILES(0, 0);

    int buf = 0;
    for (int k0 = 0; k0 < DMODEL; k0 += 16) {
        asm volatile("cp.async.wait_group 0;" ::: "memory");
        __syncthreads();
        if (k0 + 16 < DMODEL) G_LOAD_TILES(buf ^ 1, k0 + 16);

        const float* pA = sA + buf * SA_SZ;
        const float* pB = sB + buf * SB_SZ;
#pragma unroll
        for (int kk = 0; kk < 16; kk += 8) {
            unsigned af[4][4], bf[4][2];
#pragma unroll
            for (int mi = 0; mi < 4; mi++) {
                int m = wm * 64 + mi * 16 + grp;
                af[mi][0] = __float_as_uint(pA[m * SA_STR + kk + tig]);
                af[mi][1] = __float_as_uint(pA[(m + 8) * SA_STR + kk + tig]);
                af[mi][2] = __float_as_uint(pA[m * SA_STR + kk + tig + 4]);
                af[mi][3] = __float_as_uint(pA[(m + 8) * SA_STR + kk + tig + 4]);
            }
#pragma unroll
            for (int nj = 0; nj < 4; nj++) {
                int n = wn * 32 + nj * 8 + grp;
                bf[nj][0] = __float_as_uint(pB[(kk + tig) * SB_STR + n]);
                bf[nj][1] = __float_as_uint(pB[(kk + tig + 4) * SB_STR + n]);
            }
#pragma unroll
            for (int mi = 0; mi < 4; mi++)
#pragma unroll
                for (int nj = 0; nj < 4; nj++)
                    MMA_TF32(acc[mi][nj], af[mi], bf[nj]);
        }
        buf ^= 1;
    }

#pragma unroll
    for (int mi = 0; mi < 4; mi++) {
        int r0 = m0 + wm * 64 + mi * 16 + grp;
#pragma unroll
        for (int nj = 0; nj < 4; nj++) {
            int c0 = n0 + wn * 32 + nj * 8 + tig * 2;
            scatter(mode, r0,     c0,     acc[mi][nj][0] + bias[c0],     out);
            scatter(mode, r0,     c0 + 1, acc[mi][nj][1] + bias[c0 + 1], out);
            scatter(mode, r0 + 8, c0,     acc[mi][nj][2] + bias[c0],     out);
            scatter(mode, r0 + 8, c0 + 1, acc[mi][nj][3] + bias[c0 + 1], out);
        }
    }
#undef G_LOAD_TILES
}

// =============================================================================
// Fused attention: block = (head-batch, 64 q rows), 512 threads, 16 warps.
// Q/K/V pre-rounded -> no CVT in MMA loops (only at P materialization).
// =============================================================================
#define OFF_Q    0                    // [q][kpacked] stride 68, 64x68
#define OFF_K    4352                 // 2 bufs of [k][n] stride 136, 64x136 each
#define OFF_P    4352                 // phase2: [q][kpacked] stride 140, 64x140
#define OFF_V    13312                // [s][d] stride 72, 128x72
#define OFF_MODS 22528
#define OFF_RED  23040                // 16 x 64
#define OFF_RMAX 24064
#define OFF_RINV 24128
#define ATTN_SMEM_WORDS 24192
#define ATTN_SMEM_BYTES (ATTN_SMEM_WORDS * 4)

extern __shared__ unsigned dsm[];

__global__ __launch_bounds__(512, 1) void attn_fused(
    const int* __restrict__ mods, const int* __restrict__ nlp)
{
    unsigned* sQ     = dsm + OFF_Q;
    float*    sK     = (float*)(dsm + OFF_K);
    unsigned* sP     = dsm + OFF_P;
    float*    sV     = (float*)(dsm + OFF_V);
    int*      s_mods = (int*)(dsm + OFF_MODS);
    float*    s_red  = (float*)(dsm + OFF_RED);
    float*    s_rmax = (float*)(dsm + OFF_RMAX);
    float*    s_rinv = (float*)(dsm + OFF_RINV);

    const int tid  = threadIdx.x;
    const int lane = tid & 31, w = tid >> 5;
    const int grp  = lane >> 2, tig = lane & 3;
    const int wm = w & 1, wn = w >> 1;          // 2 x 8 warp grid
    const int batch = blockIdx.y;
    const int m0 = blockIdx.x * 64;
    const int bt = batch / NHEAD, h = batch % NHEAD;

    const float* __restrict__ Qp = g_Q  + (size_t)batch * SEQ * HDIM;
    const float* __restrict__ Kp = g_Kt + (size_t)batch * HDIM * SEQ;
    const float* __restrict__ Vp = g_V  + (size_t)batch * SEQ * HDIM;
    const unsigned smem_u32 = (unsigned)__cvta_generic_to_shared(dsm);

    s_mods[tid] = mods[tid];
    {   // Q tile, packed-pair layout (values already tf32-rounded)
        int q = tid >> 3, j = tid & 7;
        const float* src = Qp + (size_t)(m0 + q) * HDIM + j * 8;
        float4 a = *(const float4*)src;
        float4 b = *(const float4*)(src + 4);
        unsigned* dst = sQ + q * 68 + j * 8;
        dst[0] = __float_as_uint(a.x); dst[1] = __float_as_uint(b.x);
        dst[2] = __float_as_uint(a.y); dst[3] = __float_as_uint(b.y);
        dst[4] = __float_as_uint(a.z); dst[5] = __float_as_uint(b.z);
        dst[6] = __float_as_uint(a.w); dst[7] = __float_as_uint(b.w);
    }

#define LOAD_K(buf, c)                                                            \
    {                                                                             \
        _Pragma("unroll")                                                         \
        for (int rep = 0; rep < 4; rep++) {                                       \
            int idx = rep * 512 + tid;                                            \
            int r = idx >> 5, c4 = (idx & 31) * 4;                                \
            cp16(smem_u32 + (unsigned)((OFF_K + (buf) * 8704 + r * 136 + c4) * 4),\
                 Kp + (size_t)r * SEQ + (c) * 128 + c4);                          \
        }                                                                         \
        asm volatile("cp.async.commit_group;" ::: "memory");                      \
    }

    LOAD_K(0, 0);

    float S[4][2][2][4];
#pragma unroll
    for (int c = 0; c < 4; c++)
#pragma unroll
        for (int i = 0; i < 2; i++)
#pragma unroll
            for (int j = 0; j < 2; j++)
#pragma unroll
                for (int e = 0; e < 4; e++) S[c][i][j][e] = 0.0f;

    const unsigned* qr0 = sQ + (wm * 32 + grp) * 68 + 2 * tig;
    const unsigned* qr1 = sQ + (wm * 32 + grp + 8) * 68 + 2 * tig;
    const unsigned* qr2 = sQ + (wm * 32 + grp + 16) * 68 + 2 * tig;
    const unsigned* qr3 = sQ + (wm * 32 + grp + 24) * 68 + 2 * tig;
    const int bn0 = wn * 16 + grp;

    // ---------------- phase 1: S = Q @ K^T ----------------
#pragma unroll
    for (int c = 0; c < 4; c++) {
        asm volatile("cp.async.wait_group 0;" ::: "memory");
        __syncthreads();
        if (c < 3) LOAD_K((c + 1) & 1, c + 1);
        const float* pK = sK + (c & 1) * 8704;
#pragma unroll
        for (int kk = 0; kk < 64; kk += 8) {
            uint2 u00 = *(const uint2*)(qr0 + kk);
            uint2 u01 = *(const uint2*)(qr1 + kk);
            uint2 u10 = *(const uint2*)(qr2 + kk);
            uint2 u11 = *(const uint2*)(qr3 + kk);
            unsigned af0[4] = {u00.x, u01.x, u00.y, u01.y};
            unsigned af1[4] = {u10.x, u11.x, u10.y, u11.y};
            unsigned bf0[2] = { __float_as_uint(pK[(kk + tig) * 136 + bn0]),
                                __float_as_uint(pK[(kk + tig + 4) * 136 + bn0]) };
            unsigned bf1[2] = { __float_as_uint(pK[(kk + tig) * 136 + bn0 + 8]),
                                __float_as_uint(pK[(kk + tig + 4) * 136 + bn0 + 8]) };
            MMA_TF32(S[c][0][0], af0, bf0);
            MMA_TF32(S[c][0][1], af0, bf1);
            MMA_TF32(S[c][1][0], af1, bf0);
            MMA_TF32(S[c][1][1], af1, bf1);
        }
    }
#undef LOAD_K

    // ---------------- mask + softmax ----------------
    const int nlat = nlp ? *nlp : 32;
    int rloc[4]; int mq[4]; bool lat[4]; float lm[4];
#pragma unroll
    for (int rr = 0; rr < 4; rr++) {
        int mi = rr >> 1, hh = rr & 1;
        rloc[rr] = wm * 32 + mi * 16 + hh * 8 + grp;
        int rg = m0 + rloc[rr];
        lat[rr] = (rg < nlat);
        mq[rr] = s_mods[rg];
        lm[rr] = -3.0e38f;
    }
#pragma unroll
    for (int c = 0; c < 4; c++)
#pragma unroll
        for (int nj = 0; nj < 2; nj++) {
            int k0 = c * 128 + wn * 16 + nj * 8 + 2 * tig;
            int md0 = s_mods[k0], md1 = s_mods[k0 + 1];
#pragma unroll
            for (int rr = 0; rr < 4; rr++) {
                int mi = rr >> 1, hh = rr & 1;
                float& s0 = S[c][mi][nj][hh * 2 + 0];
                float& s1 = S[c][mi][nj][hh * 2 + 1];
                if (!(lat[rr] || mq[rr] == md0)) s0 = -3.0e38f;
                if (!(lat[rr] || mq[rr] == md1)) s1 = -3.0e38f;
                lm[rr] = fmaxf(lm[rr], fmaxf(s0, s1));
            }
        }
#pragma unroll
    for (int rr = 0; rr < 4; rr++) {
        lm[rr] = fmaxf(lm[rr], __shfl_xor_sync(0xffffffffu, lm[rr], 1));
        lm[rr] = fmaxf(lm[rr], __shfl_xor_sync(0xffffffffu, lm[rr], 2));
    }
    if (tig == 0) {
#pragma unroll
        for (int rr = 0; rr < 4; rr++) s_red[w * 64 + rloc[rr]] = lm[rr];
    }
    __syncthreads();
    if (tid < 64) {
        int wsel = tid >> 5;
        float m = -3.0e38f;
#pragma unroll
        for (int j = 0; j < 8; j++) m = fmaxf(m, s_red[(2 * j + wsel) * 64 + tid]);
        s_rmax[tid] = m;
    }
    __syncthreads();

    float rm[4], ls[4];
#pragma unroll
    for (int rr = 0; rr < 4; rr++) { rm[rr] = s_rmax[rloc[rr]]; ls[rr] = 0.0f; }
#pragma unroll
    for (int c = 0; c < 4; c++)
#pragma unroll
        for (int nj = 0; nj < 2; nj++)
#pragma unroll
            for (int rr = 0; rr < 4; rr++) {
                int mi = rr >> 1, hh = rr & 1;
                float& s0 = S[c][mi][nj][hh * 2 + 0];
                float& s1 = S[c][mi][nj][hh * 2 + 1];
                s0 = __expf(s0 - rm[rr]);
                s1 = __expf(s1 - rm[rr]);
                ls[rr] += s0 + s1;
            }
#pragma unroll
    for (int rr = 0; rr < 4; rr++) {
        ls[rr] += __shfl_xor_sync(0xffffffffu, ls[rr], 1);
        ls[rr] += __shfl_xor_sync(0xffffffffu, ls[rr], 2);
    }
    if (tig == 0) {
#pragma unroll
        for (int rr = 0; rr < 4; rr++) s_red[w * 64 + rloc[rr]] = ls[rr];
    }
    __syncthreads();
    if (tid < 64) {
        int wsel = tid >> 5;
        float s = 0.0f;
#pragma unroll
        for (int j = 0; j < 8; j++) s += s_red[(2 * j + wsel) * 64 + tid];
        s_rinv[tid] = 1.0f / s;
    }

    // ---------------- phase 2: O = P @ V ----------------
    float O0[4] = {0.0f, 0.0f, 0.0f, 0.0f};
    float O1[4] = {0.0f, 0.0f, 0.0f, 0.0f};
    const int vn = wn * 8 + grp;
    const unsigned* pr0 = sP + (wm * 32 + grp) * 140 + 2 * tig;
    const unsigned* pr1 = sP + (wm * 32 + grp + 8) * 140 + 2 * tig;
    const unsigned* pr2 = sP + (wm * 32 + grp + 16) * 140 + 2 * tig;
    const unsigned* pr3 = sP + (wm * 32 + grp + 24) * 140 + 2 * tig;

#pragma unroll
    for (int c = 0; c < 4; c++) {
        __syncthreads();
#pragma unroll
        for (int rep = 0; rep < 4; rep++) {
            int idx = rep * 512 + tid;
            int r = idx >> 4, d4 = (idx & 15) * 4;
            cp16(smem_u32 + (unsigned)((OFF_V + r * 72 + d4) * 4),
                 Vp + (size_t)(c * 128 + r) * HDIM + d4);
        }
        asm volatile("cp.async.commit_group;" ::: "memory");
#pragma unroll
        for (int nj = 0; nj < 2; nj++)
#pragma unroll
            for (int b = 0; b < 2; b++) {
                int kl = wn * 16 + nj * 8 + 2 * tig + b;
                int pos = (kl >> 3) * 8 + (kl & 3) * 2 + ((kl >> 2) & 1);
#pragma unroll
                for (int rr = 0; rr < 4; rr++) {
                    int mi = rr >> 1, hh = rr & 1;
                    sP[rloc[rr] * 140 + pos] = f2tf(S[c][mi][nj][hh * 2 + b]);
                }
            }
        asm volatile("cp.async.wait_group 0;" ::: "memory");
        __syncthreads();
#pragma unroll
        for (int kk = 0; kk < 128; kk += 8) {
            uint2 u00 = *(const uint2*)(pr0 + kk);
            uint2 u01 = *(const uint2*)(pr1 + kk);
            uint2 u10 = *(const uint2*)(pr2 + kk);
            uint2 u11 = *(const uint2*)(pr3 + kk);
            unsigned af0[4] = {u00.x, u01.x, u00.y, u01.y};
            unsigned af1[4] = {u10.x, u11.x, u10.y, u11.y};
            unsigned bf[2] = { __float_as_uint(sV[(kk + tig) * 72 + vn]),
                               __float_as_uint(sV[(kk + tig + 4) * 72 + vn]) };
            MMA_TF32(O0, af0, bf);
            MMA_TF32(O1, af1, bf);
        }
    }

    // epilogue: normalize, tf32-round, write ctx
#pragma unroll
    for (int rr = 0; rr < 4; rr++) {
        int mi = rr >> 1, hh = rr & 1;
        const float* Osel = mi ? O1 : O0;
        float inv = s_rinv[rloc[rr]];
        float2 val;
        val.x = f2tff(Osel[hh * 2 + 0] * inv);
        val.y = f2tff(Osel[hh * 2 + 1] * inv);
        int d0 = wn * 8 + 2 * tig;
        *(float2*)(g_CTX + (size_t)(bt * SEQ + m0 + rloc[rr]) * DMODEL
                   + h * HDIM + d0) = val;
    }
}

// =============================================================================
extern "C" void kernel_launch(void* const* d_in, const int* in_sizes, int n_in,
                              void* d_out, int out_size)
{
    const float* x  = (const float*)d_in[0];
    const float* Wq = (const float*)d_in[1];
    const float* bq = (const float*)d_in[2];
    const float* Wk = (const float*)d_in[3];
    const float* bk = (const float*)d_in[4];
    const float* Wv = (const float*)d_in[5];
    const float* bv = (const float*)d_in[6];
    const float* Wo = (const float*)d_in[7];
    const float* bo = (const float*)d_in[8];
    const int* mods = (const int*)d_in[9];
    const int* nlp  = (n_in > 10) ? (const int*)d_in[10] : nullptr;
    float* out = (float*)d_out;

    cudaFuncSetAttribute(attn_fused, cudaFuncAttributeMaxDynamicSharedMemorySize,
                         ATTN_SMEM_BYTES);

    prep_round<<<(PREP_QUADS + 255) / 256, 256>>>(x, Wq, Wk, Wv, Wo);
    gemm768<<<dim3(6, 128), 256>>>(bq, nullptr, 0);
    gemm768<<<dim3(6, 128), 256>>>(bk, nullptr, 1);
    gemm768<<<dim3(6, 128), 256>>>(bv, nullptr, 2);
    attn_fused<<<dim3(SEQ / 64, NBATCH), 512, ATTN_SMEM_BYTES>>>(mods, nlp);
    gemm768<<<dim3(6, 128), 256>>>(bo, out, 3);
}